// round 3
// baseline (speedup 1.0000x reference)
#include <cuda_runtime.h>

// LSTM: B=4096, T=512, I=10, H=32, O=1. Gate order i,f,g,o.
// Block = 64 threads (2 warps), NB=4 batch elements per block.
// Gate-split warp specialization: warp0 owns gates (i,f), warp1 owns (g,o).
// Each warp keeps its 2 gates' weights in REGISTERS as f32x2 pairs
// (even/odd-j halves accumulate in the two halves of each u64 accumulator).
// Activated gate values are exchanged via smem; both warps redundantly
// compute the identical c/h update (bit-identical -> deterministic).

#define B_TOT 4096
#define T_LEN 512
#define I_DIM 10
#define H_DIM 32
#define NB 4

typedef unsigned long long u64;

__device__ __forceinline__ u64 fma2(u64 a, u64 b, u64 c) {
    u64 d;
    asm("fma.rn.f32x2 %0, %1, %2, %3;" : "=l"(d) : "l"(a), "l"(b), "l"(c));
    return d;
}
__device__ __forceinline__ u64 pack2(float lo, float hi) {
    u64 d;
    asm("mov.b64 %0, {%1, %2};" : "=l"(d) : "f"(lo), "f"(hi));
    return d;
}
__device__ __forceinline__ void unpack2(u64 v, float& lo, float& hi) {
    asm("mov.b64 {%0, %1}, %2;" : "=f"(lo), "=f"(hi) : "l"(v));
}
__device__ __forceinline__ float ex2f(float x) {
    float y; asm("ex2.approx.f32 %0, %1;" : "=f"(y) : "f"(x)); return y;
}
__device__ __forceinline__ float rcpf(float x) {
    float y; asm("rcp.approx.f32 %0, %1;" : "=f"(y) : "f"(x)); return y;
}
__device__ __forceinline__ float sigf(float x) {
    return rcpf(1.0f + ex2f(-1.4426950408889634f * x));
}
__device__ __forceinline__ float tanh_f(float x) {
    return fmaf(2.0f, rcpf(1.0f + ex2f(-2.8853900817779268f * x)), -1.0f);
}

__global__ __launch_bounds__(64, 7) void lstm_gatesplit_kernel(
    const float* __restrict__ x,    // [B, T, I]
    const float* __restrict__ Wih,  // [4H, I]
    const float* __restrict__ Whh,  // [4H, H]
    const float* __restrict__ bih,  // [4H]
    const float* __restrict__ bhh,  // [4H]
    const float* __restrict__ Wd,   // [1, H]
    const float* __restrict__ bd,   // [1]
    float* __restrict__ out)        // [B, 1]
{
    __shared__ __align__(16) float sH[NB][H_DIM];       // 512 B
    __shared__ __align__(16) float sX[NB][12];          // padded to 48B rows
    __shared__ u64 sG[2][NB][32];                       // activated gate pairs, 2 KB

    const int lane = threadIdx.x & 31;
    const int w = threadIdx.x >> 5;       // 0: gates (i,f), 1: gates (g,o)
    const int b0 = blockIdx.x * NB;
    const int ga = 2 * w;                  // first gate this warp owns
    const int gb = 2 * w + 1;              // second gate

    // ---- Prologue: this warp's weights into registers (paired over j/i) ----
    u64 wha[16], whb[16];                  // recurrent, 16 j-pairs per gate
#pragma unroll
    for (int p = 0; p < 16; p++) {
        wha[p] = *(const u64*)&Whh[(ga * 32 + lane) * H_DIM + 2 * p];
        whb[p] = *(const u64*)&Whh[(gb * 32 + lane) * H_DIM + 2 * p];
    }
    u64 wxa[5], wxb[5];                    // input, 5 i-pairs per gate
#pragma unroll
    for (int p = 0; p < 5; p++) {
        wxa[p] = *(const u64*)&Wih[(ga * 32 + lane) * I_DIM + 2 * p];
        wxb[p] = *(const u64*)&Wih[(gb * 32 + lane) * I_DIM + 2 * p];
    }
    // Bias folded into accumulator init: acc = (bias, 0); final = lo+hi.
    const u64 bias_a = pack2(bih[ga * 32 + lane] + bhh[ga * 32 + lane], 0.0f);
    const u64 bias_b = pack2(bih[gb * 32 + lane] + bhh[gb * 32 + lane], 0.0f);

    float h[NB], c[NB];
#pragma unroll
    for (int k = 0; k < NB; k++) { h[k] = 0.0f; c[k] = 0.0f; }

    // x prefetch: warp w serves batches 2w, 2w+1 (lanes < I_DIM).
    float xv0 = 0.0f, xv1 = 0.0f;
    const float* xp0 = x + ((b0 + 2 * w + 0) * T_LEN) * I_DIM + lane;
    const float* xp1 = x + ((b0 + 2 * w + 1) * T_LEN) * I_DIM + lane;
    if (lane < I_DIM) { xv0 = *xp0; xv1 = *xp1; }

    for (int t = 0; t < T_LEN; t++) {
        // Publish h (each warp stores its 2 batches; copies are identical)
        sH[2 * w + 0][lane] = h[2 * w + 0];
        sH[2 * w + 1][lane] = h[2 * w + 1];
        if (lane < I_DIM) {
            sX[2 * w + 0][lane] = xv0;
            sX[2 * w + 1][lane] = xv1;
        }
        __syncthreads();

        // Prefetch next timestep's x (overlaps the gate math below).
        if (t + 1 < T_LEN) {
            xp0 += I_DIM; xp1 += I_DIM;
            if (lane < I_DIM) { xv0 = *xp0; xv1 = *xp1; }
        }

        u64 aa[NB], ab[NB];
#pragma unroll
        for (int k = 0; k < NB; k++) { aa[k] = bias_a; ab[k] = bias_b; }

#pragma unroll
        for (int k = 0; k < NB; k++) {
            // recurrent: 8 x 16B uniform broadcast chunks = 16 h-pairs
#pragma unroll
            for (int q = 0; q < 8; q++) {
                const ulonglong2 hp = *(const ulonglong2*)&sH[k][4 * q];
                aa[k] = fma2(wha[2 * q],     hp.x, aa[k]);
                ab[k] = fma2(whb[2 * q],     hp.x, ab[k]);
                aa[k] = fma2(wha[2 * q + 1], hp.y, aa[k]);
                ab[k] = fma2(whb[2 * q + 1], hp.y, ab[k]);
            }
            // input: 5 x-pairs
            const ulonglong2 xq0 = *(const ulonglong2*)&sX[k][0];
            const ulonglong2 xq1 = *(const ulonglong2*)&sX[k][4];
            const u64 xq2 = *(const u64*)&sX[k][8];
            aa[k] = fma2(wxa[0], xq0.x, aa[k]);
            ab[k] = fma2(wxb[0], xq0.x, ab[k]);
            aa[k] = fma2(wxa[1], xq0.y, aa[k]);
            ab[k] = fma2(wxb[1], xq0.y, ab[k]);
            aa[k] = fma2(wxa[2], xq1.x, aa[k]);
            ab[k] = fma2(wxb[2], xq1.x, ab[k]);
            aa[k] = fma2(wxa[3], xq1.y, aa[k]);
            ab[k] = fma2(wxb[3], xq1.y, ab[k]);
            aa[k] = fma2(wxa[4], xq2, aa[k]);
            ab[k] = fma2(wxb[4], xq2, ab[k]);
        }

        // Activations for this warp's gates, publish packed (va, vb).
        float va[NB], vb[NB];
        if (w == 0) {
#pragma unroll
            for (int k = 0; k < NB; k++) {
                float lo, hi;
                unpack2(aa[k], lo, hi); va[k] = sigf(lo + hi);   // i
                unpack2(ab[k], lo, hi); vb[k] = sigf(lo + hi);   // f
            }
        } else {
#pragma unroll
            for (int k = 0; k < NB; k++) {
                float lo, hi;
                unpack2(aa[k], lo, hi); va[k] = tanh_f(lo + hi); // g
                unpack2(ab[k], lo, hi); vb[k] = sigf(lo + hi);   // o
            }
        }
#pragma unroll
        for (int k = 0; k < NB; k++)
            sG[w][k][lane] = pack2(va[k], vb[k]);
        __syncthreads();

        // Redundant identical state update in both warps.
#pragma unroll
        for (int k = 0; k < NB; k++) {
            float oa, ob;
            unpack2(sG[1 - w][k][lane], oa, ob);
            const float gi = (w == 0) ? va[k] : oa;
            const float gf = (w == 0) ? vb[k] : ob;
            const float gg = (w == 0) ? oa : va[k];
            const float go = (w == 0) ? ob : vb[k];
            c[k] = fmaf(gf, c[k], gi * gg);
            h[k] = go * tanh_f(c[k]);
        }
    }

    // Final dense: out[b] = sum_l h[b][l]*Wd[l] + bd. Each warp writes 2.
    const float wd = Wd[lane];
    const float bdv = bd[0];
#pragma unroll
    for (int j = 0; j < 2; j++) {
        const int k = 2 * w + j;
        float p = h[k] * wd;
#pragma unroll
        for (int off = 16; off; off >>= 1)
            p += __shfl_xor_sync(0xffffffffu, p, off);
        if (lane == 0) out[b0 + k] = p + bdv;
    }
}

extern "C" void kernel_launch(void* const* d_in, const int* in_sizes, int n_in,
                              void* d_out, int out_size) {
    const float* x   = (const float*)d_in[0];
    const float* Wih = (const float*)d_in[1];
    const float* Whh = (const float*)d_in[2];
    const float* bih = (const float*)d_in[3];
    const float* bhh = (const float*)d_in[4];
    const float* Wd  = (const float*)d_in[5];
    const float* bd  = (const float*)d_in[6];
    (void)in_sizes; (void)n_in; (void)out_size;

    lstm_gatesplit_kernel<<<B_TOT / NB, 64>>>(x, Wih, Whh, bih, bhh, Wd, bd,
                                              (float*)d_out);
}